// round 12
// baseline (speedup 1.0000x reference)
#include <cuda_runtime.h>
#include <cuda_fp16.h>
#include <cstdint>
#include <cstddef>

// ---------------------------------------------------------------------------
// KANLayer as one big GEMM (mma.sync fp16, single product):
//   out[4096,2048] = X_ext[4096,18432] @ W_ext[2048,18432]^T
// Round 12: combine folded into the persistent kernel (last-contributor
// atomic pattern, deterministic ascending-j sum). GEMM/prep identical to
// round 11 (at HMMA issue floor / DRAM floor respectively).
// ---------------------------------------------------------------------------

#define B_ROWS 4096
#define O_COLS 2048
#define I_FEAT 2048
#define G_KNOT 8
#define K_EXT  (I_FEAT + I_FEAT * G_KNOT)   // 18432
#define K_CHUNK 128
#define N_CHUNKS (K_EXT / K_CHUNK)           // 144 per tile

#define N_SM 148
#define N_TAIL_TILES 108                     // tiles 148..255
#define TAIL_UNITS (N_TAIL_TILES * N_CHUNKS) // 15552

#define M_TILE 256
#define N_TILE 128
#define THREADS 512
// stage: [A0 32K][A1 32K][B0 16K][B1 16K] = 96KB
#define STAGE_BYTES 98304
#define SMEM_BYTES (2 * STAGE_BYTES)         // 196608

__device__ __half g_A[(size_t)B_ROWS * K_EXT];
__device__ __half g_B[(size_t)O_COLS * K_EXT];
// per-CTA partial tiles: 148 CTAs x 2 slots x (256x128) fp32
__device__ float g_part[(size_t)N_SM * 2 * M_TILE * N_TILE];
// per-tail-tile arrival counters (reset by prep each replay)
__device__ int g_tile_cnt[N_TAIL_TILES];

// ------------------------------ PTX helpers --------------------------------
__device__ __forceinline__ uint32_t smem_to_u32(const void* p) {
    uint32_t a;
    asm("{ .reg .u64 t; cvta.to.shared.u64 t, %1; cvt.u32.u64 %0, t; }"
        : "=r"(a) : "l"(p));
    return a;
}

#define CP_ASYNC16(dst, src) \
    asm volatile("cp.async.cg.shared.global [%0], [%1], 16;" \
                 :: "r"(dst), "l"(src))
#define CP_COMMIT() asm volatile("cp.async.commit_group;" ::: "memory")
#define CP_WAIT1()  asm volatile("cp.async.wait_group 1;" ::: "memory")

#define LDSM4(r, addr) \
    asm volatile("ldmatrix.sync.aligned.m8n8.x4.shared.b16 {%0,%1,%2,%3}, [%4];" \
        : "=r"((r)[0]), "=r"((r)[1]), "=r"((r)[2]), "=r"((r)[3]) : "r"(addr))

#define MMA_F16(d, a, b) \
    asm volatile("mma.sync.aligned.m16n8k16.row.col.f32.f16.f16.f32 " \
        "{%0,%1,%2,%3}, {%4,%5,%6,%7}, {%8,%9}, {%0,%1,%2,%3};" \
        : "+f"((d)[0]), "+f"((d)[1]), "+f"((d)[2]), "+f"((d)[3]) \
        : "r"((a)[0]), "r"((a)[1]), "r"((a)[2]), "r"((a)[3]), \
          "r"((b)[0]), "r"((b)[1]))

// --------------------------- preprocessing (merged) -------------------------

struct alignas(16) Pack8 { __half v[8]; };

// grid (K_EXT/2048, O_COLS + B_ROWS), 256 thr; thread -> 8 consecutive k
__global__ void prep_kernel(const float* __restrict__ x,
                            const float* __restrict__ base_w,
                            const float* __restrict__ spline_w,
                            const float* __restrict__ knots) {
    // reset tail-tile counters once per launch (stream-ordered before GEMM)
    if (blockIdx.x == 0 && blockIdx.y == 0 && threadIdx.x < N_TAIL_TILES)
        g_tile_cnt[threadIdx.x] = 0;

    const int row = blockIdx.y;
    const int k8 = (blockIdx.x * 256 + threadIdx.x) * 8;
    float v[8];
    if (row < O_COLS) {                      // ---- W_ext row ----
        const int o = row;
        if (blockIdx.x == 0) {
            const float4* p = reinterpret_cast<const float4*>(base_w + (size_t)o * I_FEAT + k8);
            float4 a = p[0], b = p[1];
            v[0]=a.x; v[1]=a.y; v[2]=a.z; v[3]=a.w; v[4]=b.x; v[5]=b.y; v[6]=b.z; v[7]=b.w;
        } else {
            const float4* p = reinterpret_cast<const float4*>(
                spline_w + (size_t)o * (I_FEAT * G_KNOT) + (k8 - I_FEAT));
            float4 a = p[0], b = p[1];
            v[0]=0.1f*a.x; v[1]=0.1f*a.y; v[2]=0.1f*a.z; v[3]=0.1f*a.w;
            v[4]=0.1f*b.x; v[5]=0.1f*b.y; v[6]=0.1f*b.z; v[7]=0.1f*b.w;
        }
        Pack8 h;
#pragma unroll
        for (int jj = 0; jj < 8; ++jj) h.v[jj] = __float2half(v[jj]);
        *reinterpret_cast<Pack8*>(&g_B[(size_t)o * K_EXT + k8]) = h;
    } else {                                 // ---- X_ext row ----
        const int b = row - O_COLS;
        if (blockIdx.x == 0) {
            const float4* p = reinterpret_cast<const float4*>(x + (size_t)b * I_FEAT + k8);
            float4 a = p[0], c = p[1];
            v[0]=a.x; v[1]=a.y; v[2]=a.z; v[3]=a.w; v[4]=c.x; v[5]=c.y; v[6]=c.z; v[7]=c.w;
        } else {
            const int i = (k8 - I_FEAT) >> 3;
            const float xv = __ldg(&x[(size_t)b * I_FEAT + i]);
            const float4 kn0 = *reinterpret_cast<const float4*>(knots);
            const float4 kn1 = *(reinterpret_cast<const float4*>(knots) + 1);
            v[0]=fmaxf(xv-kn0.x,0.f); v[1]=fmaxf(xv-kn0.y,0.f);
            v[2]=fmaxf(xv-kn0.z,0.f); v[3]=fmaxf(xv-kn0.w,0.f);
            v[4]=fmaxf(xv-kn1.x,0.f); v[5]=fmaxf(xv-kn1.y,0.f);
            v[6]=fmaxf(xv-kn1.z,0.f); v[7]=fmaxf(xv-kn1.w,0.f);
        }
        Pack8 h;
#pragma unroll
        for (int jj = 0; jj < 8; ++jj) h.v[jj] = __float2half(v[jj]);
        *reinterpret_cast<Pack8*>(&g_A[(size_t)b * K_EXT + k8]) = h;
    }
}

// ------------------------------ GEMM core -----------------------------------
__device__ __forceinline__ void tile_coords(int p, int& mb, int& nb) {
    const int grp = p >> 6;
    const int inb = p & 63;
    mb = grp * 4 + (inb & 3);
    nb = inb >> 2;
}

// Load one 128-col K-chunk of A(256 rows) + B(128 rows) into a stage. 512 thr.
__device__ __forceinline__ void load_chunk(const __half* gA, const __half* gB,
                                           uint32_t st, int tid) {
#pragma unroll
    for (int h = 0; h < 2; ++h) {
#pragma unroll
        for (int i = 0; i < 4; ++i) {        // A: 2048 16B pieces per half
            const int idx = tid + i * THREADS;
            const int row = idx >> 3;
            const int sub = idx & 7;
            const uint32_t off = (uint32_t)(row * 128 + sub * 16);
            const uint32_t sw = off ^ ((off >> 3) & 0x70u);
            CP_ASYNC16(st + h * 32768 + sw,
                       reinterpret_cast<const char*>(gA) +
                           (size_t)row * (K_EXT * 2) + h * 128 + sub * 16);
        }
#pragma unroll
        for (int i = 0; i < 2; ++i) {        // B: 1024 pieces per half
            const int idx = tid + i * THREADS;
            const int row = idx >> 3;
            const int sub = idx & 7;
            const uint32_t off = (uint32_t)(row * 128 + sub * 16);
            const uint32_t sw = off ^ ((off >> 3) & 0x70u);
            CP_ASYNC16(st + 65536 + h * 16384 + sw,
                       reinterpret_cast<const char*>(gB) +
                           (size_t)row * (K_EXT * 2) + h * 128 + sub * 16);
        }
    }
}

// Compute chunks [c0, c1) of tile (m0, n0); write into dst (stride dstride).
// 16 warps: wm = warp&3 (64 M-rows each), wn = warp>>2 (32 N-cols each).
__device__ __forceinline__ void gemm_range(size_t m0, size_t n0, int c0, int c1,
                                           float* __restrict__ dst, int dstride,
                                           uint32_t sm0, int tid) {
    const int lane = tid & 31;
    const int warp = tid >> 5;
    const int wm = warp & 3;
    const int wn = warp >> 2;

    const __half* pA = g_A + m0 * K_EXT;
    const __half* pB = g_B + n0 * K_EXT;

    float acc[4][4][4] = {};

    const int a_lr = (lane & 7) | (((lane >> 3) & 1) << 3);
    const int a_ko = (lane >> 4) << 4;
    const int b_lr = (lane & 7) | (((lane >> 4) & 1) << 3);
    const int b_ko = ((lane >> 3) & 1) << 4;
    const uint32_t xorl = (uint32_t)((lane & 7) << 4);

    uint32_t a_rowoff[4], b_rowoff[2];
#pragma unroll
    for (int mt = 0; mt < 4; ++mt)
        a_rowoff[mt] = (uint32_t)((wm * 64 + mt * 16 + a_lr) * 128);
#pragma unroll
    for (int nt2 = 0; nt2 < 2; ++nt2)
        b_rowoff[nt2] = (uint32_t)((wn * 32 + nt2 * 16 + b_lr) * 128);

    load_chunk(pA + (size_t)c0 * K_CHUNK, pB + (size_t)c0 * K_CHUNK,
               sm0 + (uint32_t)((c0 & 1)) * STAGE_BYTES, tid);
    CP_COMMIT();

    for (int c = c0; c < c1; ++c) {
        if (c + 1 < c1) {
            const size_t k1 = (size_t)(c + 1) * K_CHUNK;
            load_chunk(pA + k1, pB + k1,
                       sm0 + (uint32_t)(((c + 1) & 1)) * STAGE_BYTES, tid);
        }
        CP_COMMIT();
        CP_WAIT1();
        __syncthreads();

        const uint32_t sb = sm0 + (uint32_t)((c & 1)) * STAGE_BYTES;

#pragma unroll
        for (int ks = 0; ks < 8; ++ks) {
            const uint32_t ha = (uint32_t)((ks >> 2) * 32768);
            const uint32_t hb = (uint32_t)((ks >> 2) * 16384);
            const uint32_t kb = (uint32_t)((ks & 3) * 32);
            const uint32_t kA = (kb + a_ko) ^ xorl;
            const uint32_t kB = (kb + b_ko) ^ xorl;

            uint32_t ah[4][4], bh[2][4];
#pragma unroll
            for (int mt = 0; mt < 4; ++mt)
                LDSM4(ah[mt], sb + ha + a_rowoff[mt] + kA);
#pragma unroll
            for (int nt2 = 0; nt2 < 2; ++nt2)
                LDSM4(bh[nt2], sb + 65536 + hb + b_rowoff[nt2] + kB);

#pragma unroll
            for (int mt = 0; mt < 4; ++mt)
#pragma unroll
                for (int nt = 0; nt < 4; ++nt)
                    MMA_F16(acc[mt][nt], ah[mt],
                            &bh[nt >> 1][(nt & 1) * 2]);
        }
        __syncthreads();
    }

    // Epilogue: direct stores (dst pre-offset to tile origin)
    const int r = lane >> 2;
    const int cp2 = (lane & 3) * 2;
#pragma unroll
    for (int mt = 0; mt < 4; ++mt) {
        const int row = wm * 64 + mt * 16 + r;
#pragma unroll
        for (int nt = 0; nt < 4; ++nt) {
            const int col = wn * 32 + nt * 8 + cp2;
            *reinterpret_cast<float2*>(&dst[(size_t)row * dstride + col]) =
                make_float2(acc[mt][nt][0], acc[mt][nt][1]);
            *reinterpret_cast<float2*>(&dst[(size_t)(row + 8) * dstride + col]) =
                make_float2(acc[mt][nt][2], acc[mt][nt][3]);
        }
    }
}

// Combine tail tile t: deterministic ascending-j sum of its segments. 512 thr.
__device__ __forceinline__ void combine_tile(int t, int tid,
                                             float* __restrict__ out) {
    const int unit0 = t * N_CHUNKS;
    const int unit1 = unit0 + N_CHUNKS;

    int j0 = (unit0 * N_SM) / TAIL_UNITS;
    while (((j0 + 1) * TAIL_UNITS) / N_SM <= unit0) ++j0;

    int mb, nb;
    tile_coords(N_SM + t, mb, nb);

#pragma unroll
    for (int it = 0; it < 8; ++it) {
        const int base = (tid + it * THREADS) * 8;   // 512*8*8 = 32768 floats
        float4 s0 = make_float4(0.f, 0.f, 0.f, 0.f);
        float4 s1 = make_float4(0.f, 0.f, 0.f, 0.f);
        for (int j = j0; j < N_SM; ++j) {
            const int sj = (j * TAIL_UNITS) / N_SM;
            if (sj >= unit1) break;
            const int sl = (sj / N_CHUNKS == t) ? 0 : 1;
            const float4* p = reinterpret_cast<const float4*>(
                g_part + ((size_t)j * 2 + sl) * (M_TILE * N_TILE) + base);
            const float4 a = p[0], b = p[1];
            s0.x += a.x; s0.y += a.y; s0.z += a.z; s0.w += a.w;
            s1.x += b.x; s1.y += b.y; s1.z += b.z; s1.w += b.w;
        }
        const int r = base >> 7;
        const int c = base & 127;
        float* o = &out[(size_t)(mb * M_TILE + r) * O_COLS + nb * N_TILE + c];
        *reinterpret_cast<float4*>(o) = s0;
        *reinterpret_cast<float4*>(o + 4) = s1;
    }
}

// Persistent kernel: CTA j = full tile j, then tail slice j (+ inline combine).
__global__ void __launch_bounds__(THREADS, 1) kan_gemm_persist(float* __restrict__ out) {
    extern __shared__ char smem[];
    __shared__ int s_do_combine;
    const uint32_t sm0 = smem_to_u32(smem);
    const int tid = threadIdx.x;
    const int j = blockIdx.x;                 // 0..147

    int mb, nb;
    tile_coords(j, mb, nb);
    gemm_range((size_t)mb * M_TILE, (size_t)nb * N_TILE, 0, N_CHUNKS,
               out + (size_t)mb * M_TILE * O_COLS + (size_t)nb * N_TILE,
               O_COLS, sm0, tid);

    // tail slice: chunk-units [j*15552/148, (j+1)*15552/148)
    int s = (j * TAIL_UNITS) / N_SM;
    const int e = ((j + 1) * TAIL_UNITS) / N_SM;
    int sl = 0;
    while (s < e) {
        const int t = s / N_CHUNKS;                       // tail tile index
        const int seg_end = min(e, (t + 1) * N_CHUNKS);
        tile_coords(N_SM + t, mb, nb);
        gemm_range((size_t)mb * M_TILE, (size_t)nb * N_TILE,
                   s - t * N_CHUNKS, seg_end - t * N_CHUNKS,
                   g_part + ((size_t)j * 2 + sl) * (M_TILE * N_TILE),
                   N_TILE, sm0, tid);

        // arrive at tile t; last contributor combines (deterministic sum)
        __threadfence();
        __syncthreads();
        if (tid == 0) {
            const int unit0 = t * N_CHUNKS;
            const int unit1 = unit0 + N_CHUNKS;
            int jj = (unit0 * N_SM) / TAIL_UNITS;
            while (((jj + 1) * TAIL_UNITS) / N_SM <= unit0) ++jj;
            int n = 0;
            for (int j2 = jj; j2 < N_SM; ++j2) {
                if ((j2 * TAIL_UNITS) / N_SM >= unit1) break;
                ++n;
            }
            const int old = atomicAdd(&g_tile_cnt[t], 1);
            s_do_combine = (old == n - 1);
        }
        __syncthreads();
        if (s_do_combine) {
            __threadfence();
            combine_tile(t, tid, out);
        }
        __syncthreads();

        s = seg_end;
        ++sl;
    }
}

// ------------------------------- launch -------------------------------------

extern "C" void kernel_launch(void* const* d_in, const int* in_sizes, int n_in,
                              void* d_out, int out_size) {
    const float* x        = (const float*)d_in[0];
    const float* base_w   = (const float*)d_in[1];
    const float* spline_w = (const float*)d_in[2];
    const float* knots    = (const float*)d_in[3];
    float* out = (float*)d_out;

    prep_kernel<<<dim3(K_EXT / 2048, O_COLS + B_ROWS), 256>>>(x, base_w, spline_w, knots);

    cudaFuncSetAttribute(kan_gemm_persist,
                         cudaFuncAttributeMaxDynamicSharedMemorySize, SMEM_BYTES);
    kan_gemm_persist<<<N_SM, THREADS, SMEM_BYTES>>>(out);
}

// round 13
// speedup vs baseline: 1.2809x; 1.2809x over previous
#include <cuda_runtime.h>
#include <cuda_fp16.h>
#include <cstdint>
#include <cstddef>

// ---------------------------------------------------------------------------
// KANLayer as one big GEMM (mma.sync fp16, single product):
//   out[4096,2048] = X_ext[4096,18432] @ W_ext[2048,18432]^T
// Round 13: byte-identical revert to round 11 (best verified: 739.5us).
// - GEMM at legacy-HMMA issue floor (persistent 148 CTAs, full tile + balanced
//   tail K-slices, 512 thr, K_CHUNK=128 double-buffered cp.async).
// - prep at DRAM floor; separate vectorized combine kernel.
// R12's inline-combine (threadfence in steady-state loop) regressed 28%: reverted.
// ---------------------------------------------------------------------------

#define B_ROWS 4096
#define O_COLS 2048
#define I_FEAT 2048
#define G_KNOT 8
#define K_EXT  (I_FEAT + I_FEAT * G_KNOT)   // 18432
#define K_CHUNK 128
#define N_CHUNKS (K_EXT / K_CHUNK)           // 144 per tile

#define N_SM 148
#define N_TAIL_TILES 108                     // tiles 148..255
#define TAIL_UNITS (N_TAIL_TILES * N_CHUNKS) // 15552

#define M_TILE 256
#define N_TILE 128
#define THREADS 512
// stage: [A0 32K][A1 32K][B0 16K][B1 16K] = 96KB
#define STAGE_BYTES 98304
#define SMEM_BYTES (2 * STAGE_BYTES)         // 196608

__device__ __half g_A[(size_t)B_ROWS * K_EXT];
__device__ __half g_B[(size_t)O_COLS * K_EXT];
// per-CTA partial tiles: 148 CTAs x 2 slots x (256x128) fp32
__device__ float g_part[(size_t)N_SM * 2 * M_TILE * N_TILE];

// ------------------------------ PTX helpers --------------------------------
__device__ __forceinline__ uint32_t smem_to_u32(const void* p) {
    uint32_t a;
    asm("{ .reg .u64 t; cvta.to.shared.u64 t, %1; cvt.u32.u64 %0, t; }"
        : "=r"(a) : "l"(p));
    return a;
}

#define CP_ASYNC16(dst, src) \
    asm volatile("cp.async.cg.shared.global [%0], [%1], 16;" \
                 :: "r"(dst), "l"(src))
#define CP_COMMIT() asm volatile("cp.async.commit_group;" ::: "memory")
#define CP_WAIT1()  asm volatile("cp.async.wait_group 1;" ::: "memory")

#define LDSM4(r, addr) \
    asm volatile("ldmatrix.sync.aligned.m8n8.x4.shared.b16 {%0,%1,%2,%3}, [%4];" \
        : "=r"((r)[0]), "=r"((r)[1]), "=r"((r)[2]), "=r"((r)[3]) : "r"(addr))

#define MMA_F16(d, a, b) \
    asm volatile("mma.sync.aligned.m16n8k16.row.col.f32.f16.f16.f32 " \
        "{%0,%1,%2,%3}, {%4,%5,%6,%7}, {%8,%9}, {%0,%1,%2,%3};" \
        : "+f"((d)[0]), "+f"((d)[1]), "+f"((d)[2]), "+f"((d)[3]) \
        : "r"((a)[0]), "r"((a)[1]), "r"((a)[2]), "r"((a)[3]), \
          "r"((b)[0]), "r"((b)[1]))

// --------------------------- preprocessing (merged) -------------------------

struct alignas(16) Pack8 { __half v[8]; };

// grid (K_EXT/2048, O_COLS + B_ROWS), 256 thr; thread -> 8 consecutive k
__global__ void prep_kernel(const float* __restrict__ x,
                            const float* __restrict__ base_w,
                            const float* __restrict__ spline_w,
                            const float* __restrict__ knots) {
    const int row = blockIdx.y;
    const int k8 = (blockIdx.x * 256 + threadIdx.x) * 8;
    float v[8];
    if (row < O_COLS) {                      // ---- W_ext row ----
        const int o = row;
        if (blockIdx.x == 0) {
            const float4* p = reinterpret_cast<const float4*>(base_w + (size_t)o * I_FEAT + k8);
            float4 a = p[0], b = p[1];
            v[0]=a.x; v[1]=a.y; v[2]=a.z; v[3]=a.w; v[4]=b.x; v[5]=b.y; v[6]=b.z; v[7]=b.w;
        } else {
            const float4* p = reinterpret_cast<const float4*>(
                spline_w + (size_t)o * (I_FEAT * G_KNOT) + (k8 - I_FEAT));
            float4 a = p[0], b = p[1];
            v[0]=0.1f*a.x; v[1]=0.1f*a.y; v[2]=0.1f*a.z; v[3]=0.1f*a.w;
            v[4]=0.1f*b.x; v[5]=0.1f*b.y; v[6]=0.1f*b.z; v[7]=0.1f*b.w;
        }
        Pack8 h;
#pragma unroll
        for (int jj = 0; jj < 8; ++jj) h.v[jj] = __float2half(v[jj]);
        *reinterpret_cast<Pack8*>(&g_B[(size_t)o * K_EXT + k8]) = h;
    } else {                                 // ---- X_ext row ----
        const int b = row - O_COLS;
        if (blockIdx.x == 0) {
            const float4* p = reinterpret_cast<const float4*>(x + (size_t)b * I_FEAT + k8);
            float4 a = p[0], c = p[1];
            v[0]=a.x; v[1]=a.y; v[2]=a.z; v[3]=a.w; v[4]=c.x; v[5]=c.y; v[6]=c.z; v[7]=c.w;
        } else {
            const int i = (k8 - I_FEAT) >> 3;
            const float xv = __ldg(&x[(size_t)b * I_FEAT + i]);
            const float4 kn0 = *reinterpret_cast<const float4*>(knots);
            const float4 kn1 = *(reinterpret_cast<const float4*>(knots) + 1);
            v[0]=fmaxf(xv-kn0.x,0.f); v[1]=fmaxf(xv-kn0.y,0.f);
            v[2]=fmaxf(xv-kn0.z,0.f); v[3]=fmaxf(xv-kn0.w,0.f);
            v[4]=fmaxf(xv-kn1.x,0.f); v[5]=fmaxf(xv-kn1.y,0.f);
            v[6]=fmaxf(xv-kn1.z,0.f); v[7]=fmaxf(xv-kn1.w,0.f);
        }
        Pack8 h;
#pragma unroll
        for (int jj = 0; jj < 8; ++jj) h.v[jj] = __float2half(v[jj]);
        *reinterpret_cast<Pack8*>(&g_A[(size_t)b * K_EXT + k8]) = h;
    }
}

// ------------------------------ GEMM core -----------------------------------
__device__ __forceinline__ void tile_coords(int p, int& mb, int& nb) {
    const int grp = p >> 6;
    const int inb = p & 63;
    mb = grp * 4 + (inb & 3);
    nb = inb >> 2;
}

// Load one 128-col K-chunk of A(256 rows) + B(128 rows) into a stage. 512 thr.
__device__ __forceinline__ void load_chunk(const __half* gA, const __half* gB,
                                           uint32_t st, int tid) {
#pragma unroll
    for (int h = 0; h < 2; ++h) {
#pragma unroll
        for (int i = 0; i < 4; ++i) {        // A: 2048 16B pieces per half
            const int idx = tid + i * THREADS;
            const int row = idx >> 3;
            const int sub = idx & 7;
            const uint32_t off = (uint32_t)(row * 128 + sub * 16);
            const uint32_t sw = off ^ ((off >> 3) & 0x70u);
            CP_ASYNC16(st + h * 32768 + sw,
                       reinterpret_cast<const char*>(gA) +
                           (size_t)row * (K_EXT * 2) + h * 128 + sub * 16);
        }
#pragma unroll
        for (int i = 0; i < 2; ++i) {        // B: 1024 pieces per half
            const int idx = tid + i * THREADS;
            const int row = idx >> 3;
            const int sub = idx & 7;
            const uint32_t off = (uint32_t)(row * 128 + sub * 16);
            const uint32_t sw = off ^ ((off >> 3) & 0x70u);
            CP_ASYNC16(st + 65536 + h * 16384 + sw,
                       reinterpret_cast<const char*>(gB) +
                           (size_t)row * (K_EXT * 2) + h * 128 + sub * 16);
        }
    }
}

// Compute chunks [c0, c1) of tile (m0, n0); write into dst (stride dstride).
// 16 warps: wm = warp&3 (64 M-rows each), wn = warp>>2 (32 N-cols each).
__device__ __forceinline__ void gemm_range(size_t m0, size_t n0, int c0, int c1,
                                           float* __restrict__ dst, int dstride,
                                           uint32_t sm0, int tid) {
    const int lane = tid & 31;
    const int warp = tid >> 5;
    const int wm = warp & 3;
    const int wn = warp >> 2;

    const __half* pA = g_A + m0 * K_EXT;
    const __half* pB = g_B + n0 * K_EXT;

    float acc[4][4][4] = {};

    const int a_lr = (lane & 7) | (((lane >> 3) & 1) << 3);
    const int a_ko = (lane >> 4) << 4;
    const int b_lr = (lane & 7) | (((lane >> 4) & 1) << 3);
    const int b_ko = ((lane >> 3) & 1) << 4;
    const uint32_t xorl = (uint32_t)((lane & 7) << 4);

    uint32_t a_rowoff[4], b_rowoff[2];
#pragma unroll
    for (int mt = 0; mt < 4; ++mt)
        a_rowoff[mt] = (uint32_t)((wm * 64 + mt * 16 + a_lr) * 128);
#pragma unroll
    for (int nt2 = 0; nt2 < 2; ++nt2)
        b_rowoff[nt2] = (uint32_t)((wn * 32 + nt2 * 16 + b_lr) * 128);

    load_chunk(pA + (size_t)c0 * K_CHUNK, pB + (size_t)c0 * K_CHUNK,
               sm0 + (uint32_t)((c0 & 1)) * STAGE_BYTES, tid);
    CP_COMMIT();

    for (int c = c0; c < c1; ++c) {
        if (c + 1 < c1) {
            const size_t k1 = (size_t)(c + 1) * K_CHUNK;
            load_chunk(pA + k1, pB + k1,
                       sm0 + (uint32_t)(((c + 1) & 1)) * STAGE_BYTES, tid);
        }
        CP_COMMIT();
        CP_WAIT1();
        __syncthreads();

        const uint32_t sb = sm0 + (uint32_t)((c & 1)) * STAGE_BYTES;

#pragma unroll
        for (int ks = 0; ks < 8; ++ks) {
            const uint32_t ha = (uint32_t)((ks >> 2) * 32768);
            const uint32_t hb = (uint32_t)((ks >> 2) * 16384);
            const uint32_t kb = (uint32_t)((ks & 3) * 32);
            const uint32_t kA = (kb + a_ko) ^ xorl;
            const uint32_t kB = (kb + b_ko) ^ xorl;

            uint32_t ah[4][4], bh[2][4];
#pragma unroll
            for (int mt = 0; mt < 4; ++mt)
                LDSM4(ah[mt], sb + ha + a_rowoff[mt] + kA);
#pragma unroll
            for (int nt2 = 0; nt2 < 2; ++nt2)
                LDSM4(bh[nt2], sb + 65536 + hb + b_rowoff[nt2] + kB);

#pragma unroll
            for (int mt = 0; mt < 4; ++mt)
#pragma unroll
                for (int nt = 0; nt < 4; ++nt)
                    MMA_F16(acc[mt][nt], ah[mt],
                            &bh[nt >> 1][(nt & 1) * 2]);
        }
        __syncthreads();
    }

    // Epilogue: direct stores (dst pre-offset to tile origin)
    const int r = lane >> 2;
    const int cp2 = (lane & 3) * 2;
#pragma unroll
    for (int mt = 0; mt < 4; ++mt) {
        const int row = wm * 64 + mt * 16 + r;
#pragma unroll
        for (int nt = 0; nt < 4; ++nt) {
            const int col = wn * 32 + nt * 8 + cp2;
            *reinterpret_cast<float2*>(&dst[(size_t)row * dstride + col]) =
                make_float2(acc[mt][nt][0], acc[mt][nt][1]);
            *reinterpret_cast<float2*>(&dst[(size_t)(row + 8) * dstride + col]) =
                make_float2(acc[mt][nt][2], acc[mt][nt][3]);
        }
    }
}

// Persistent kernel: CTA j = full tile j, then tail slice j.
__global__ void __launch_bounds__(THREADS, 1) kan_gemm_persist(float* __restrict__ out) {
    extern __shared__ char smem[];
    const uint32_t sm0 = smem_to_u32(smem);
    const int tid = threadIdx.x;
    const int j = blockIdx.x;                 // 0..147

    int mb, nb;
    tile_coords(j, mb, nb);
    gemm_range((size_t)mb * M_TILE, (size_t)nb * N_TILE, 0, N_CHUNKS,
               out + (size_t)mb * M_TILE * O_COLS + (size_t)nb * N_TILE,
               O_COLS, sm0, tid);

    // tail slice: chunk-units [j*15552/148, (j+1)*15552/148)
    int s = (j * TAIL_UNITS) / N_SM;
    const int e = ((j + 1) * TAIL_UNITS) / N_SM;
    int sl = 0;
    while (s < e) {
        const int t = s / N_CHUNKS;                       // tail tile index
        const int seg_end = min(e, (t + 1) * N_CHUNKS);
        tile_coords(N_SM + t, mb, nb);
        gemm_range((size_t)mb * M_TILE, (size_t)nb * N_TILE,
                   s - t * N_CHUNKS, seg_end - t * N_CHUNKS,
                   g_part + ((size_t)j * 2 + sl) * (M_TILE * N_TILE),
                   N_TILE, sm0, tid);
        s = seg_end;
        ++sl;
    }
}

// Combine: tail tile t = sum of its 1..3 partial segments (ascending j).
// Vectorized: 8 elems/thread via 2x float4. grid = 108*16 blocks, 256 thr.
__global__ void __launch_bounds__(256) kan_combine(float* __restrict__ out) {
    const int t = blockIdx.x >> 4;                        // tail tile 0..107
    const int base = (((blockIdx.x & 15) << 8) | threadIdx.x) * 8;  // 0..32760
    const int unit0 = t * N_CHUNKS;
    const int unit1 = unit0 + N_CHUNKS;

    int j = (unit0 * N_SM) / TAIL_UNITS;
    while (((j + 1) * TAIL_UNITS) / N_SM <= unit0) ++j;

    float4 s0 = make_float4(0.f, 0.f, 0.f, 0.f);
    float4 s1 = make_float4(0.f, 0.f, 0.f, 0.f);
    while (j < N_SM) {
        const int sj = (j * TAIL_UNITS) / N_SM;
        if (sj >= unit1) break;
        const int sl = (sj / N_CHUNKS == t) ? 0 : 1;
        const float4* p = reinterpret_cast<const float4*>(
            g_part + ((size_t)j * 2 + sl) * (M_TILE * N_TILE) + base);
        const float4 a = p[0], b = p[1];
        s0.x += a.x; s0.y += a.y; s0.z += a.z; s0.w += a.w;
        s1.x += b.x; s1.y += b.y; s1.z += b.z; s1.w += b.w;
        ++j;
    }

    int mb, nb;
    tile_coords(N_SM + t, mb, nb);
    const int r = base >> 7;          // row in 256x128 tile
    const int c = base & 127;         // col (8-aligned)
    float* o = &out[(size_t)(mb * M_TILE + r) * O_COLS + nb * N_TILE + c];
    *reinterpret_cast<float4*>(o) = s0;
    *reinterpret_cast<float4*>(o + 4) = s1;
}

// ------------------------------- launch -------------------------------------

extern "C" void kernel_launch(void* const* d_in, const int* in_sizes, int n_in,
                              void* d_out, int out_size) {
    const float* x        = (const float*)d_in[0];
    const float* base_w   = (const float*)d_in[1];
    const float* spline_w = (const float*)d_in[2];
    const float* knots    = (const float*)d_in[3];
    float* out = (float*)d_out;

    prep_kernel<<<dim3(K_EXT / 2048, O_COLS + B_ROWS), 256>>>(x, base_w, spline_w, knots);

    cudaFuncSetAttribute(kan_gemm_persist,
                         cudaFuncAttributeMaxDynamicSharedMemorySize, SMEM_BYTES);
    kan_gemm_persist<<<N_SM, THREADS, SMEM_BYTES>>>(out);
    kan_combine<<<N_TAIL_TILES * 16, 256>>>(out);
}

// round 14
// speedup vs baseline: 1.2936x; 1.0099x over previous
#include <cuda_runtime.h>
#include <cuda_fp16.h>
#include <cstdint>
#include <cstddef>

// ---------------------------------------------------------------------------
// KANLayer as one big GEMM (mma.sync fp16, single product):
//   out[4096,2048] = X_ext[4096,18432] @ W_ext[2048,18432]^T
// Round 14: GEMM/combine byte-identical to round 13 (banked 739.1us).
// Prep processes 2 rows/block (MLP x2, half the blocks) to push its DRAM
// utilization from 67.5% toward the 80% demonstrated in round 5.
// ---------------------------------------------------------------------------

#define B_ROWS 4096
#define O_COLS 2048
#define I_FEAT 2048
#define G_KNOT 8
#define K_EXT  (I_FEAT + I_FEAT * G_KNOT)   // 18432
#define K_CHUNK 128
#define N_CHUNKS (K_EXT / K_CHUNK)           // 144 per tile

#define N_SM 148
#define N_TAIL_TILES 108                     // tiles 148..255
#define TAIL_UNITS (N_TAIL_TILES * N_CHUNKS) // 15552

#define M_TILE 256
#define N_TILE 128
#define THREADS 512
// stage: [A0 32K][A1 32K][B0 16K][B1 16K] = 96KB
#define STAGE_BYTES 98304
#define SMEM_BYTES (2 * STAGE_BYTES)         // 196608

__device__ __half g_A[(size_t)B_ROWS * K_EXT];
__device__ __half g_B[(size_t)O_COLS * K_EXT];
// per-CTA partial tiles: 148 CTAs x 2 slots x (256x128) fp32
__device__ float g_part[(size_t)N_SM * 2 * M_TILE * N_TILE];

// ------------------------------ PTX helpers --------------------------------
__device__ __forceinline__ uint32_t smem_to_u32(const void* p) {
    uint32_t a;
    asm("{ .reg .u64 t; cvta.to.shared.u64 t, %1; cvt.u32.u64 %0, t; }"
        : "=r"(a) : "l"(p));
    return a;
}

#define CP_ASYNC16(dst, src) \
    asm volatile("cp.async.cg.shared.global [%0], [%1], 16;" \
                 :: "r"(dst), "l"(src))
#define CP_COMMIT() asm volatile("cp.async.commit_group;" ::: "memory")
#define CP_WAIT1()  asm volatile("cp.async.wait_group 1;" ::: "memory")

#define LDSM4(r, addr) \
    asm volatile("ldmatrix.sync.aligned.m8n8.x4.shared.b16 {%0,%1,%2,%3}, [%4];" \
        : "=r"((r)[0]), "=r"((r)[1]), "=r"((r)[2]), "=r"((r)[3]) : "r"(addr))

#define MMA_F16(d, a, b) \
    asm volatile("mma.sync.aligned.m16n8k16.row.col.f32.f16.f16.f32 " \
        "{%0,%1,%2,%3}, {%4,%5,%6,%7}, {%8,%9}, {%0,%1,%2,%3};" \
        : "+f"((d)[0]), "+f"((d)[1]), "+f"((d)[2]), "+f"((d)[3]) \
        : "r"((a)[0]), "r"((a)[1]), "r"((a)[2]), "r"((a)[3]), \
          "r"((b)[0]), "r"((b)[1]))

// --------------------------- preprocessing (merged) -------------------------

struct alignas(16) Pack8 { __half v[8]; };

// grid (K_EXT/2048, (O_COLS + B_ROWS)/2), 256 thr.
// Each block handles TWO rows (2*by, 2*by+1); each thread 8 consecutive k per
// row. Both rows' loads are issued before converts/stores -> MLP x2.
__global__ void prep_kernel(const float* __restrict__ x,
                            const float* __restrict__ base_w,
                            const float* __restrict__ spline_w,
                            const float* __restrict__ knots) {
    const int row0 = blockIdx.y * 2;
    const int k8 = (blockIdx.x * 256 + threadIdx.x) * 8;
    float v[2][8];

    if (row0 < O_COLS) {                     // ---- W_ext rows ----
        if (blockIdx.x == 0) {
            float4 a[2], b[2];
#pragma unroll
            for (int rr = 0; rr < 2; ++rr) {
                const float4* p = reinterpret_cast<const float4*>(
                    base_w + (size_t)(row0 + rr) * I_FEAT + k8);
                a[rr] = p[0]; b[rr] = p[1];
            }
#pragma unroll
            for (int rr = 0; rr < 2; ++rr) {
                v[rr][0]=a[rr].x; v[rr][1]=a[rr].y; v[rr][2]=a[rr].z; v[rr][3]=a[rr].w;
                v[rr][4]=b[rr].x; v[rr][5]=b[rr].y; v[rr][6]=b[rr].z; v[rr][7]=b[rr].w;
            }
        } else {
            float4 a[2], b[2];
#pragma unroll
            for (int rr = 0; rr < 2; ++rr) {
                const float4* p = reinterpret_cast<const float4*>(
                    spline_w + (size_t)(row0 + rr) * (I_FEAT * G_KNOT) + (k8 - I_FEAT));
                a[rr] = p[0]; b[rr] = p[1];
            }
#pragma unroll
            for (int rr = 0; rr < 2; ++rr) {
                v[rr][0]=0.1f*a[rr].x; v[rr][1]=0.1f*a[rr].y;
                v[rr][2]=0.1f*a[rr].z; v[rr][3]=0.1f*a[rr].w;
                v[rr][4]=0.1f*b[rr].x; v[rr][5]=0.1f*b[rr].y;
                v[rr][6]=0.1f*b[rr].z; v[rr][7]=0.1f*b[rr].w;
            }
        }
#pragma unroll
        for (int rr = 0; rr < 2; ++rr) {
            Pack8 h;
#pragma unroll
            for (int jj = 0; jj < 8; ++jj) h.v[jj] = __float2half(v[rr][jj]);
            *reinterpret_cast<Pack8*>(&g_B[(size_t)(row0 + rr) * K_EXT + k8]) = h;
        }
    } else {                                 // ---- X_ext rows ----
        const int b0 = row0 - O_COLS;
        if (blockIdx.x == 0) {
            float4 a[2], c[2];
#pragma unroll
            for (int rr = 0; rr < 2; ++rr) {
                const float4* p = reinterpret_cast<const float4*>(
                    x + (size_t)(b0 + rr) * I_FEAT + k8);
                a[rr] = p[0]; c[rr] = p[1];
            }
#pragma unroll
            for (int rr = 0; rr < 2; ++rr) {
                v[rr][0]=a[rr].x; v[rr][1]=a[rr].y; v[rr][2]=a[rr].z; v[rr][3]=a[rr].w;
                v[rr][4]=c[rr].x; v[rr][5]=c[rr].y; v[rr][6]=c[rr].z; v[rr][7]=c[rr].w;
            }
        } else {
            const int i = (k8 - I_FEAT) >> 3;
            float xv[2];
#pragma unroll
            for (int rr = 0; rr < 2; ++rr)
                xv[rr] = __ldg(&x[(size_t)(b0 + rr) * I_FEAT + i]);
            const float4 kn0 = *reinterpret_cast<const float4*>(knots);
            const float4 kn1 = *(reinterpret_cast<const float4*>(knots) + 1);
#pragma unroll
            for (int rr = 0; rr < 2; ++rr) {
                v[rr][0]=fmaxf(xv[rr]-kn0.x,0.f); v[rr][1]=fmaxf(xv[rr]-kn0.y,0.f);
                v[rr][2]=fmaxf(xv[rr]-kn0.z,0.f); v[rr][3]=fmaxf(xv[rr]-kn0.w,0.f);
                v[rr][4]=fmaxf(xv[rr]-kn1.x,0.f); v[rr][5]=fmaxf(xv[rr]-kn1.y,0.f);
                v[rr][6]=fmaxf(xv[rr]-kn1.z,0.f); v[rr][7]=fmaxf(xv[rr]-kn1.w,0.f);
            }
        }
#pragma unroll
        for (int rr = 0; rr < 2; ++rr) {
            Pack8 h;
#pragma unroll
            for (int jj = 0; jj < 8; ++jj) h.v[jj] = __float2half(v[rr][jj]);
            *reinterpret_cast<Pack8*>(&g_A[(size_t)(b0 + rr) * K_EXT + k8]) = h;
        }
    }
}

// ------------------------------ GEMM core -----------------------------------
__device__ __forceinline__ void tile_coords(int p, int& mb, int& nb) {
    const int grp = p >> 6;
    const int inb = p & 63;
    mb = grp * 4 + (inb & 3);
    nb = inb >> 2;
}

// Load one 128-col K-chunk of A(256 rows) + B(128 rows) into a stage. 512 thr.
__device__ __forceinline__ void load_chunk(const __half* gA, const __half* gB,
                                           uint32_t st, int tid) {
#pragma unroll
    for (int h = 0; h < 2; ++h) {
#pragma unroll
        for (int i = 0; i < 4; ++i) {        // A: 2048 16B pieces per half
            const int idx = tid + i * THREADS;
            const int row = idx >> 3;
            const int sub = idx & 7;
            const uint32_t off = (uint32_t)(row * 128 + sub * 16);
            const uint32_t sw = off ^ ((off >> 3) & 0x70u);
            CP_ASYNC16(st + h * 32768 + sw,
                       reinterpret_cast<const char*>(gA) +
                           (size_t)row * (K_EXT * 2) + h * 128 + sub * 16);
        }
#pragma unroll
        for (int i = 0; i < 2; ++i) {        // B: 1024 pieces per half
            const int idx = tid + i * THREADS;
            const int row = idx >> 3;
            const int sub = idx & 7;
            const uint32_t off = (uint32_t)(row * 128 + sub * 16);
            const uint32_t sw = off ^ ((off >> 3) & 0x70u);
            CP_ASYNC16(st + 65536 + h * 16384 + sw,
                       reinterpret_cast<const char*>(gB) +
                           (size_t)row * (K_EXT * 2) + h * 128 + sub * 16);
        }
    }
}

// Compute chunks [c0, c1) of tile (m0, n0); write into dst (stride dstride).
// 16 warps: wm = warp&3 (64 M-rows each), wn = warp>>2 (32 N-cols each).
__device__ __forceinline__ void gemm_range(size_t m0, size_t n0, int c0, int c1,
                                           float* __restrict__ dst, int dstride,
                                           uint32_t sm0, int tid) {
    const int lane = tid & 31;
    const int warp = tid >> 5;
    const int wm = warp & 3;
    const int wn = warp >> 2;

    const __half* pA = g_A + m0 * K_EXT;
    const __half* pB = g_B + n0 * K_EXT;

    float acc[4][4][4] = {};

    const int a_lr = (lane & 7) | (((lane >> 3) & 1) << 3);
    const int a_ko = (lane >> 4) << 4;
    const int b_lr = (lane & 7) | (((lane >> 4) & 1) << 3);
    const int b_ko = ((lane >> 3) & 1) << 4;
    const uint32_t xorl = (uint32_t)((lane & 7) << 4);

    uint32_t a_rowoff[4], b_rowoff[2];
#pragma unroll
    for (int mt = 0; mt < 4; ++mt)
        a_rowoff[mt] = (uint32_t)((wm * 64 + mt * 16 + a_lr) * 128);
#pragma unroll
    for (int nt2 = 0; nt2 < 2; ++nt2)
        b_rowoff[nt2] = (uint32_t)((wn * 32 + nt2 * 16 + b_lr) * 128);

    load_chunk(pA + (size_t)c0 * K_CHUNK, pB + (size_t)c0 * K_CHUNK,
               sm0 + (uint32_t)((c0 & 1)) * STAGE_BYTES, tid);
    CP_COMMIT();

    for (int c = c0; c < c1; ++c) {
        if (c + 1 < c1) {
            const size_t k1 = (size_t)(c + 1) * K_CHUNK;
            load_chunk(pA + k1, pB + k1,
                       sm0 + (uint32_t)(((c + 1) & 1)) * STAGE_BYTES, tid);
        }
        CP_COMMIT();
        CP_WAIT1();
        __syncthreads();

        const uint32_t sb = sm0 + (uint32_t)((c & 1)) * STAGE_BYTES;

#pragma unroll
        for (int ks = 0; ks < 8; ++ks) {
            const uint32_t ha = (uint32_t)((ks >> 2) * 32768);
            const uint32_t hb = (uint32_t)((ks >> 2) * 16384);
            const uint32_t kb = (uint32_t)((ks & 3) * 32);
            const uint32_t kA = (kb + a_ko) ^ xorl;
            const uint32_t kB = (kb + b_ko) ^ xorl;

            uint32_t ah[4][4], bh[2][4];
#pragma unroll
            for (int mt = 0; mt < 4; ++mt)
                LDSM4(ah[mt], sb + ha + a_rowoff[mt] + kA);
#pragma unroll
            for (int nt2 = 0; nt2 < 2; ++nt2)
                LDSM4(bh[nt2], sb + 65536 + hb + b_rowoff[nt2] + kB);

#pragma unroll
            for (int mt = 0; mt < 4; ++mt)
#pragma unroll
                for (int nt = 0; nt < 4; ++nt)
                    MMA_F16(acc[mt][nt], ah[mt],
                            &bh[nt >> 1][(nt & 1) * 2]);
        }
        __syncthreads();
    }

    // Epilogue: direct stores (dst pre-offset to tile origin)
    const int r = lane >> 2;
    const int cp2 = (lane & 3) * 2;
#pragma unroll
    for (int mt = 0; mt < 4; ++mt) {
        const int row = wm * 64 + mt * 16 + r;
#pragma unroll
        for (int nt = 0; nt < 4; ++nt) {
            const int col = wn * 32 + nt * 8 + cp2;
            *reinterpret_cast<float2*>(&dst[(size_t)row * dstride + col]) =
                make_float2(acc[mt][nt][0], acc[mt][nt][1]);
            *reinterpret_cast<float2*>(&dst[(size_t)(row + 8) * dstride + col]) =
                make_float2(acc[mt][nt][2], acc[mt][nt][3]);
        }
    }
}

// Persistent kernel: CTA j = full tile j, then tail slice j.
__global__ void __launch_bounds__(THREADS, 1) kan_gemm_persist(float* __restrict__ out) {
    extern __shared__ char smem[];
    const uint32_t sm0 = smem_to_u32(smem);
    const int tid = threadIdx.x;
    const int j = blockIdx.x;                 // 0..147

    int mb, nb;
    tile_coords(j, mb, nb);
    gemm_range((size_t)mb * M_TILE, (size_t)nb * N_TILE, 0, N_CHUNKS,
               out + (size_t)mb * M_TILE * O_COLS + (size_t)nb * N_TILE,
               O_COLS, sm0, tid);

    // tail slice: chunk-units [j*15552/148, (j+1)*15552/148)
    int s = (j * TAIL_UNITS) / N_SM;
    const int e = ((j + 1) * TAIL_UNITS) / N_SM;
    int sl = 0;
    while (s < e) {
        const int t = s / N_CHUNKS;                       // tail tile index
        const int seg_end = min(e, (t + 1) * N_CHUNKS);
        tile_coords(N_SM + t, mb, nb);
        gemm_range((size_t)mb * M_TILE, (size_t)nb * N_TILE,
                   s - t * N_CHUNKS, seg_end - t * N_CHUNKS,
                   g_part + ((size_t)j * 2 + sl) * (M_TILE * N_TILE),
                   N_TILE, sm0, tid);
        s = seg_end;
        ++sl;
    }
}

// Combine: tail tile t = sum of its 1..3 partial segments (ascending j).
// Vectorized: 8 elems/thread via 2x float4. grid = 108*16 blocks, 256 thr.
__global__ void __launch_bounds__(256) kan_combine(float* __restrict__ out) {
    const int t = blockIdx.x >> 4;                        // tail tile 0..107
    const int base = (((blockIdx.x & 15) << 8) | threadIdx.x) * 8;  // 0..32760
    const int unit0 = t * N_CHUNKS;
    const int unit1 = unit0 + N_CHUNKS;

    int j = (unit0 * N_SM) / TAIL_UNITS;
    while (((j + 1) * TAIL_UNITS) / N_SM <= unit0) ++j;

    float4 s0 = make_float4(0.f, 0.f, 0.f, 0.f);
    float4 s1 = make_float4(0.f, 0.f, 0.f, 0.f);
    while (j < N_SM) {
        const int sj = (j * TAIL_UNITS) / N_SM;
        if (sj >= unit1) break;
        const int sl = (sj / N_CHUNKS == t) ? 0 : 1;
        const float4* p = reinterpret_cast<const float4*>(
            g_part + ((size_t)j * 2 + sl) * (M_TILE * N_TILE) + base);
        const float4 a = p[0], b = p[1];
        s0.x += a.x; s0.y += a.y; s0.z += a.z; s0.w += a.w;
        s1.x += b.x; s1.y += b.y; s1.z += b.z; s1.w += b.w;
        ++j;
    }

    int mb, nb;
    tile_coords(N_SM + t, mb, nb);
    const int r = base >> 7;          // row in 256x128 tile
    const int c = base & 127;         // col (8-aligned)
    float* o = &out[(size_t)(mb * M_TILE + r) * O_COLS + nb * N_TILE + c];
    *reinterpret_cast<float4*>(o) = s0;
    *reinterpret_cast<float4*>(o + 4) = s1;
}

// ------------------------------- launch -------------------------------------

extern "C" void kernel_launch(void* const* d_in, const int* in_sizes, int n_in,
                              void* d_out, int out_size) {
    const float* x        = (const float*)d_in[0];
    const float* base_w   = (const float*)d_in[1];
    const float* spline_w = (const float*)d_in[2];
    const float* knots    = (const float*)d_in[3];
    float* out = (float*)d_out;

    prep_kernel<<<dim3(K_EXT / 2048, (O_COLS + B_ROWS) / 2), 256>>>(
        x, base_w, spline_w, knots);

    cudaFuncSetAttribute(kan_gemm_persist,
                         cudaFuncAttributeMaxDynamicSharedMemorySize, SMEM_BYTES);
    kan_gemm_persist<<<N_SM, THREADS, SMEM_BYTES>>>(out);
    kan_combine<<<N_TAIL_TILES * 16, 256>>>(out);
}

// round 15
// speedup vs baseline: 1.2940x; 1.0003x over previous
#include <cuda_runtime.h>
#include <cuda_fp16.h>
#include <cstdint>
#include <cstddef>

// ---------------------------------------------------------------------------
// KANLayer as one big GEMM (mma.sync fp16, single product):
//   out[4096,2048] = X_ext[4096,18432] @ W_ext[2048,18432]^T
// Round 15: GEMM/combine byte-identical to round 14 (banked 731.8us).
// Prep processes 4 rows/block (MLP x4, quarter the blocks) to close the last
// gap to the ~80% DRAM ceiling. Everything else unchanged.
// ---------------------------------------------------------------------------

#define B_ROWS 4096
#define O_COLS 2048
#define I_FEAT 2048
#define G_KNOT 8
#define K_EXT  (I_FEAT + I_FEAT * G_KNOT)   // 18432
#define K_CHUNK 128
#define N_CHUNKS (K_EXT / K_CHUNK)           // 144 per tile

#define N_SM 148
#define N_TAIL_TILES 108                     // tiles 148..255
#define TAIL_UNITS (N_TAIL_TILES * N_CHUNKS) // 15552

#define M_TILE 256
#define N_TILE 128
#define THREADS 512
// stage: [A0 32K][A1 32K][B0 16K][B1 16K] = 96KB
#define STAGE_BYTES 98304
#define SMEM_BYTES (2 * STAGE_BYTES)         // 196608

__device__ __half g_A[(size_t)B_ROWS * K_EXT];
__device__ __half g_B[(size_t)O_COLS * K_EXT];
// per-CTA partial tiles: 148 CTAs x 2 slots x (256x128) fp32
__device__ float g_part[(size_t)N_SM * 2 * M_TILE * N_TILE];

// ------------------------------ PTX helpers --------------------------------
__device__ __forceinline__ uint32_t smem_to_u32(const void* p) {
    uint32_t a;
    asm("{ .reg .u64 t; cvta.to.shared.u64 t, %1; cvt.u32.u64 %0, t; }"
        : "=r"(a) : "l"(p));
    return a;
}

#define CP_ASYNC16(dst, src) \
    asm volatile("cp.async.cg.shared.global [%0], [%1], 16;" \
                 :: "r"(dst), "l"(src))
#define CP_COMMIT() asm volatile("cp.async.commit_group;" ::: "memory")
#define CP_WAIT1()  asm volatile("cp.async.wait_group 1;" ::: "memory")

#define LDSM4(r, addr) \
    asm volatile("ldmatrix.sync.aligned.m8n8.x4.shared.b16 {%0,%1,%2,%3}, [%4];" \
        : "=r"((r)[0]), "=r"((r)[1]), "=r"((r)[2]), "=r"((r)[3]) : "r"(addr))

#define MMA_F16(d, a, b) \
    asm volatile("mma.sync.aligned.m16n8k16.row.col.f32.f16.f16.f32 " \
        "{%0,%1,%2,%3}, {%4,%5,%6,%7}, {%8,%9}, {%0,%1,%2,%3};" \
        : "+f"((d)[0]), "+f"((d)[1]), "+f"((d)[2]), "+f"((d)[3]) \
        : "r"((a)[0]), "r"((a)[1]), "r"((a)[2]), "r"((a)[3]), \
          "r"((b)[0]), "r"((b)[1]))

// --------------------------- preprocessing (merged) -------------------------

struct alignas(16) Pack8 { __half v[8]; };

// grid (K_EXT/2048, (O_COLS + B_ROWS)/4), 256 thr.
// Each block handles FOUR rows (4*by .. 4*by+3); each thread 8 consecutive k
// per row. All rows' loads issued before converts/stores -> MLP x4.
__global__ void prep_kernel(const float* __restrict__ x,
                            const float* __restrict__ base_w,
                            const float* __restrict__ spline_w,
                            const float* __restrict__ knots) {
    const int row0 = blockIdx.y * 4;
    const int k8 = (blockIdx.x * 256 + threadIdx.x) * 8;
    float v[4][8];

    if (row0 < O_COLS) {                     // ---- W_ext rows ----
        if (blockIdx.x == 0) {
            float4 a[4], b[4];
#pragma unroll
            for (int rr = 0; rr < 4; ++rr) {
                const float4* p = reinterpret_cast<const float4*>(
                    base_w + (size_t)(row0 + rr) * I_FEAT + k8);
                a[rr] = p[0]; b[rr] = p[1];
            }
#pragma unroll
            for (int rr = 0; rr < 4; ++rr) {
                v[rr][0]=a[rr].x; v[rr][1]=a[rr].y; v[rr][2]=a[rr].z; v[rr][3]=a[rr].w;
                v[rr][4]=b[rr].x; v[rr][5]=b[rr].y; v[rr][6]=b[rr].z; v[rr][7]=b[rr].w;
            }
        } else {
            float4 a[4], b[4];
#pragma unroll
            for (int rr = 0; rr < 4; ++rr) {
                const float4* p = reinterpret_cast<const float4*>(
                    spline_w + (size_t)(row0 + rr) * (I_FEAT * G_KNOT) + (k8 - I_FEAT));
                a[rr] = p[0]; b[rr] = p[1];
            }
#pragma unroll
            for (int rr = 0; rr < 4; ++rr) {
                v[rr][0]=0.1f*a[rr].x; v[rr][1]=0.1f*a[rr].y;
                v[rr][2]=0.1f*a[rr].z; v[rr][3]=0.1f*a[rr].w;
                v[rr][4]=0.1f*b[rr].x; v[rr][5]=0.1f*b[rr].y;
                v[rr][6]=0.1f*b[rr].z; v[rr][7]=0.1f*b[rr].w;
            }
        }
#pragma unroll
        for (int rr = 0; rr < 4; ++rr) {
            Pack8 h;
#pragma unroll
            for (int jj = 0; jj < 8; ++jj) h.v[jj] = __float2half(v[rr][jj]);
            *reinterpret_cast<Pack8*>(&g_B[(size_t)(row0 + rr) * K_EXT + k8]) = h;
        }
    } else {                                 // ---- X_ext rows ----
        const int b0 = row0 - O_COLS;
        if (blockIdx.x == 0) {
            float4 a[4], c[4];
#pragma unroll
            for (int rr = 0; rr < 4; ++rr) {
                const float4* p = reinterpret_cast<const float4*>(
                    x + (size_t)(b0 + rr) * I_FEAT + k8);
                a[rr] = p[0]; c[rr] = p[1];
            }
#pragma unroll
            for (int rr = 0; rr < 4; ++rr) {
                v[rr][0]=a[rr].x; v[rr][1]=a[rr].y; v[rr][2]=a[rr].z; v[rr][3]=a[rr].w;
                v[rr][4]=c[rr].x; v[rr][5]=c[rr].y; v[rr][6]=c[rr].z; v[rr][7]=c[rr].w;
            }
        } else {
            const int i = (k8 - I_FEAT) >> 3;
            float xv[4];
#pragma unroll
            for (int rr = 0; rr < 4; ++rr)
                xv[rr] = __ldg(&x[(size_t)(b0 + rr) * I_FEAT + i]);
            const float4 kn0 = *reinterpret_cast<const float4*>(knots);
            const float4 kn1 = *(reinterpret_cast<const float4*>(knots) + 1);
#pragma unroll
            for (int rr = 0; rr < 4; ++rr) {
                v[rr][0]=fmaxf(xv[rr]-kn0.x,0.f); v[rr][1]=fmaxf(xv[rr]-kn0.y,0.f);
                v[rr][2]=fmaxf(xv[rr]-kn0.z,0.f); v[rr][3]=fmaxf(xv[rr]-kn0.w,0.f);
                v[rr][4]=fmaxf(xv[rr]-kn1.x,0.f); v[rr][5]=fmaxf(xv[rr]-kn1.y,0.f);
                v[rr][6]=fmaxf(xv[rr]-kn1.z,0.f); v[rr][7]=fmaxf(xv[rr]-kn1.w,0.f);
            }
        }
#pragma unroll
        for (int rr = 0; rr < 4; ++rr) {
            Pack8 h;
#pragma unroll
            for (int jj = 0; jj < 8; ++jj) h.v[jj] = __float2half(v[rr][jj]);
            *reinterpret_cast<Pack8*>(&g_A[(size_t)(b0 + rr) * K_EXT + k8]) = h;
        }
    }
}

// ------------------------------ GEMM core -----------------------------------
__device__ __forceinline__ void tile_coords(int p, int& mb, int& nb) {
    const int grp = p >> 6;
    const int inb = p & 63;
    mb = grp * 4 + (inb & 3);
    nb = inb >> 2;
}

// Load one 128-col K-chunk of A(256 rows) + B(128 rows) into a stage. 512 thr.
__device__ __forceinline__ void load_chunk(const __half* gA, const __half* gB,
                                           uint32_t st, int tid) {
#pragma unroll
    for (int h = 0; h < 2; ++h) {
#pragma unroll
        for (int i = 0; i < 4; ++i) {        // A: 2048 16B pieces per half
            const int idx = tid + i * THREADS;
            const int row = idx >> 3;
            const int sub = idx & 7;
            const uint32_t off = (uint32_t)(row * 128 + sub * 16);
            const uint32_t sw = off ^ ((off >> 3) & 0x70u);
            CP_ASYNC16(st + h * 32768 + sw,
                       reinterpret_cast<const char*>(gA) +
                           (size_t)row * (K_EXT * 2) + h * 128 + sub * 16);
        }
#pragma unroll
        for (int i = 0; i < 2; ++i) {        // B: 1024 pieces per half
            const int idx = tid + i * THREADS;
            const int row = idx >> 3;
            const int sub = idx & 7;
            const uint32_t off = (uint32_t)(row * 128 + sub * 16);
            const uint32_t sw = off ^ ((off >> 3) & 0x70u);
            CP_ASYNC16(st + 65536 + h * 16384 + sw,
                       reinterpret_cast<const char*>(gB) +
                           (size_t)row * (K_EXT * 2) + h * 128 + sub * 16);
        }
    }
}

// Compute chunks [c0, c1) of tile (m0, n0); write into dst (stride dstride).
// 16 warps: wm = warp&3 (64 M-rows each), wn = warp>>2 (32 N-cols each).
__device__ __forceinline__ void gemm_range(size_t m0, size_t n0, int c0, int c1,
                                           float* __restrict__ dst, int dstride,
                                           uint32_t sm0, int tid) {
    const int lane = tid & 31;
    const int warp = tid >> 5;
    const int wm = warp & 3;
    const int wn = warp >> 2;

    const __half* pA = g_A + m0 * K_EXT;
    const __half* pB = g_B + n0 * K_EXT;

    float acc[4][4][4] = {};

    const int a_lr = (lane & 7) | (((lane >> 3) & 1) << 3);
    const int a_ko = (lane >> 4) << 4;
    const int b_lr = (lane & 7) | (((lane >> 4) & 1) << 3);
    const int b_ko = ((lane >> 3) & 1) << 4;
    const uint32_t xorl = (uint32_t)((lane & 7) << 4);

    uint32_t a_rowoff[4], b_rowoff[2];
#pragma unroll
    for (int mt = 0; mt < 4; ++mt)
        a_rowoff[mt] = (uint32_t)((wm * 64 + mt * 16 + a_lr) * 128);
#pragma unroll
    for (int nt2 = 0; nt2 < 2; ++nt2)
        b_rowoff[nt2] = (uint32_t)((wn * 32 + nt2 * 16 + b_lr) * 128);

    load_chunk(pA + (size_t)c0 * K_CHUNK, pB + (size_t)c0 * K_CHUNK,
               sm0 + (uint32_t)((c0 & 1)) * STAGE_BYTES, tid);
    CP_COMMIT();

    for (int c = c0; c < c1; ++c) {
        if (c + 1 < c1) {
            const size_t k1 = (size_t)(c + 1) * K_CHUNK;
            load_chunk(pA + k1, pB + k1,
                       sm0 + (uint32_t)(((c + 1) & 1)) * STAGE_BYTES, tid);
        }
        CP_COMMIT();
        CP_WAIT1();
        __syncthreads();

        const uint32_t sb = sm0 + (uint32_t)((c & 1)) * STAGE_BYTES;

#pragma unroll
        for (int ks = 0; ks < 8; ++ks) {
            const uint32_t ha = (uint32_t)((ks >> 2) * 32768);
            const uint32_t hb = (uint32_t)((ks >> 2) * 16384);
            const uint32_t kb = (uint32_t)((ks & 3) * 32);
            const uint32_t kA = (kb + a_ko) ^ xorl;
            const uint32_t kB = (kb + b_ko) ^ xorl;

            uint32_t ah[4][4], bh[2][4];
#pragma unroll
            for (int mt = 0; mt < 4; ++mt)
                LDSM4(ah[mt], sb + ha + a_rowoff[mt] + kA);
#pragma unroll
            for (int nt2 = 0; nt2 < 2; ++nt2)
                LDSM4(bh[nt2], sb + 65536 + hb + b_rowoff[nt2] + kB);

#pragma unroll
            for (int mt = 0; mt < 4; ++mt)
#pragma unroll
                for (int nt = 0; nt < 4; ++nt)
                    MMA_F16(acc[mt][nt], ah[mt],
                            &bh[nt >> 1][(nt & 1) * 2]);
        }
        __syncthreads();
    }

    // Epilogue: direct stores (dst pre-offset to tile origin)
    const int r = lane >> 2;
    const int cp2 = (lane & 3) * 2;
#pragma unroll
    for (int mt = 0; mt < 4; ++mt) {
        const int row = wm * 64 + mt * 16 + r;
#pragma unroll
        for (int nt = 0; nt < 4; ++nt) {
            const int col = wn * 32 + nt * 8 + cp2;
            *reinterpret_cast<float2*>(&dst[(size_t)row * dstride + col]) =
                make_float2(acc[mt][nt][0], acc[mt][nt][1]);
            *reinterpret_cast<float2*>(&dst[(size_t)(row + 8) * dstride + col]) =
                make_float2(acc[mt][nt][2], acc[mt][nt][3]);
        }
    }
}

// Persistent kernel: CTA j = full tile j, then tail slice j.
__global__ void __launch_bounds__(THREADS, 1) kan_gemm_persist(float* __restrict__ out) {
    extern __shared__ char smem[];
    const uint32_t sm0 = smem_to_u32(smem);
    const int tid = threadIdx.x;
    const int j = blockIdx.x;                 // 0..147

    int mb, nb;
    tile_coords(j, mb, nb);
    gemm_range((size_t)mb * M_TILE, (size_t)nb * N_TILE, 0, N_CHUNKS,
               out + (size_t)mb * M_TILE * O_COLS + (size_t)nb * N_TILE,
               O_COLS, sm0, tid);

    // tail slice: chunk-units [j*15552/148, (j+1)*15552/148)
    int s = (j * TAIL_UNITS) / N_SM;
    const int e = ((j + 1) * TAIL_UNITS) / N_SM;
    int sl = 0;
    while (s < e) {
        const int t = s / N_CHUNKS;                       // tail tile index
        const int seg_end = min(e, (t + 1) * N_CHUNKS);
        tile_coords(N_SM + t, mb, nb);
        gemm_range((size_t)mb * M_TILE, (size_t)nb * N_TILE,
                   s - t * N_CHUNKS, seg_end - t * N_CHUNKS,
                   g_part + ((size_t)j * 2 + sl) * (M_TILE * N_TILE),
                   N_TILE, sm0, tid);
        s = seg_end;
        ++sl;
    }
}

// Combine: tail tile t = sum of its 1..3 partial segments (ascending j).
// Vectorized: 8 elems/thread via 2x float4. grid = 108*16 blocks, 256 thr.
__global__ void __launch_bounds__(256) kan_combine(float* __restrict__ out) {
    const int t = blockIdx.x >> 4;                        // tail tile 0..107
    const int base = (((blockIdx.x & 15) << 8) | threadIdx.x) * 8;  // 0..32760
    const int unit0 = t * N_CHUNKS;
    const int unit1 = unit0 + N_CHUNKS;

    int j = (unit0 * N_SM) / TAIL_UNITS;
    while (((j + 1) * TAIL_UNITS) / N_SM <= unit0) ++j;

    float4 s0 = make_float4(0.f, 0.f, 0.f, 0.f);
    float4 s1 = make_float4(0.f, 0.f, 0.f, 0.f);
    while (j < N_SM) {
        const int sj = (j * TAIL_UNITS) / N_SM;
        if (sj >= unit1) break;
        const int sl = (sj / N_CHUNKS == t) ? 0 : 1;
        const float4* p = reinterpret_cast<const float4*>(
            g_part + ((size_t)j * 2 + sl) * (M_TILE * N_TILE) + base);
        const float4 a = p[0], b = p[1];
        s0.x += a.x; s0.y += a.y; s0.z += a.z; s0.w += a.w;
        s1.x += b.x; s1.y += b.y; s1.z += b.z; s1.w += b.w;
        ++j;
    }

    int mb, nb;
    tile_coords(N_SM + t, mb, nb);
    const int r = base >> 7;          // row in 256x128 tile
    const int c = base & 127;         // col (8-aligned)
    float* o = &out[(size_t)(mb * M_TILE + r) * O_COLS + nb * N_TILE + c];
    *reinterpret_cast<float4*>(o) = s0;
    *reinterpret_cast<float4*>(o + 4) = s1;
}

// ------------------------------- launch -------------------------------------

extern "C" void kernel_launch(void* const* d_in, const int* in_sizes, int n_in,
                              void* d_out, int out_size) {
    const float* x        = (const float*)d_in[0];
    const float* base_w   = (const float*)d_in[1];
    const float* spline_w = (const float*)d_in[2];
    const float* knots    = (const float*)d_in[3];
    float* out = (float*)d_out;

    prep_kernel<<<dim3(K_EXT / 2048, (O_COLS + B_ROWS) / 4), 256>>>(
        x, base_w, spline_w, knots);

    cudaFuncSetAttribute(kan_gemm_persist,
                         cudaFuncAttributeMaxDynamicSharedMemorySize, SMEM_BYTES);
    kan_gemm_persist<<<N_SM, THREADS, SMEM_BYTES>>>(out);
    kan_combine<<<N_TAIL_TILES * 16, 256>>>(out);
}